// round 8
// baseline (speedup 1.0000x reference)
#include <cuda_runtime.h>

// SpatialTransformer: out = trilinear_sample(src, identity_grid + flow), border clamp.
// src:  [1,1,160,192,160] f32   d_in[0]
// flow: [1,3,160,192,160] f32   d_in[1]  (channel-planar: d,h,w displacement)
// grid: identity meshgrid       d_in[2]  (IGNORED - recomputed from indices)
// out:  [1,1,160,192,160] f32
//
// Math collapse (verified, rel_err 2.6e-5):
//   ux = (w + flow[2]) * W/(W-1) - 0.5 ; clamp [0, W-1]; trilinear w/ clamped +1.
//
// R7 state: float2 pair-fetch (x0&~1 covers both x-corners for even x0, 50%
// predicated scalar fix-up) = ~6 L1 wavefronts/voxel. That's the fixed cost.
// R8 move: the limiter is L1 *feed rate* (L1=82%, occ=68%, issue=27%), caused
// by ZB=4 register pressure (40 regs -> 6 blocks/SM). Go to 1 voxel/thread +
// __launch_bounds__(256, 8) to hit 2048 threads/SM and saturate L1tex.

#define DD 160
#define HH 192
#define WW 160
#define PLANE (HH * WW)
#define NN (DD * HH * WW)

__global__ __launch_bounds__(256, 8) void st_warp_f2o_kernel(
    const float* __restrict__ src,
    const float* __restrict__ flow,
    float* __restrict__ out)
{
    const int idx = blockIdx.x * blockDim.x + threadIdx.x;
    if (idx >= NN) return;

    const int w = idx % WW;
    const int t = idx / WW;
    const int h = t % HH;
    const int d = t / HH;

    const float sx = (float)WW / (float)(WW - 1);
    const float sy = (float)HH / (float)(HH - 1);
    const float sz = (float)DD / (float)(DD - 1);

    // coalesced scalar loads of the three flow planes
    const float fd = __ldg(flow + idx);            // D-displacement
    const float fh = __ldg(flow + NN + idx);       // H-displacement
    const float fw = __ldg(flow + 2 * NN + idx);   // W-displacement

    float ux = ((float)w + fw) * sx - 0.5f;
    float uy = ((float)h + fh) * sy - 0.5f;
    float uz = ((float)d + fd) * sz - 0.5f;

    ux = fminf(fmaxf(ux, 0.0f), (float)(WW - 1));
    uy = fminf(fmaxf(uy, 0.0f), (float)(HH - 1));
    uz = fminf(fmaxf(uz, 0.0f), (float)(DD - 1));

    // coords >= 0 -> truncation == floor
    const int x0 = (int)ux;
    const int y0 = (int)uy;
    const int z0 = (int)uz;
    const float ax = ux - (float)x0;
    const float ay = uy - (float)y0;
    const float az = uz - (float)z0;

    const int x1 = min(x0 + 1, WW - 1);
    const int y1 = min(y0 + 1, HH - 1);
    const int z1 = min(z0 + 1, DD - 1);

    const int x0a = x0 & ~1;            // 8B-aligned pair start
    const bool odd = (x0 & 1) != 0;

    const int zy00 = (z0 * HH + y0) * WW;
    const int zy01 = (z0 * HH + y1) * WW;
    const int zy10 = (z1 * HH + y0) * WW;
    const int zy11 = (z1 * HH + y1) * WW;

    const float2 v00 = __ldg((const float2*)(src + zy00 + x0a));
    const float2 v01 = __ldg((const float2*)(src + zy01 + x0a));
    const float2 v10 = __ldg((const float2*)(src + zy10 + x0a));
    const float2 v11 = __ldg((const float2*)(src + zy11 + x0a));

    // predicated fix-up loads for odd x0 (pair straddles float2 boundary)
    float e00 = v00.y, e01 = v01.y, e10 = v10.y, e11 = v11.y;
    if (odd) e00 = __ldg(src + zy00 + x1);
    if (odd) e01 = __ldg(src + zy01 + x1);
    if (odd) e10 = __ldg(src + zy10 + x1);
    if (odd) e11 = __ldg(src + zy11 + x1);

    const float l00 = odd ? v00.y : v00.x;
    const float l01 = odd ? v01.y : v01.x;
    const float l10 = odd ? v10.y : v10.x;
    const float l11 = odd ? v11.y : v11.x;

    const float c00 = fmaf(ax, e00 - l00, l00);
    const float c01 = fmaf(ax, e01 - l01, l01);
    const float c10 = fmaf(ax, e10 - l10, l10);
    const float c11 = fmaf(ax, e11 - l11, l11);

    const float c0 = fmaf(ay, c01 - c00, c00);
    const float c1 = fmaf(ay, c11 - c10, c10);
    out[idx] = fmaf(az, c1 - c0, c0);
}

extern "C" void kernel_launch(void* const* d_in, const int* in_sizes, int n_in,
                              void* d_out, int out_size)
{
    const float* src  = (const float*)d_in[0];
    const float* flow = (const float*)d_in[1];
    // d_in[2] (identity grid) intentionally unused — recomputed from indices.
    float* out = (float*)d_out;

    const int threads = 256;
    const int blocks = (NN + threads - 1) / threads;
    st_warp_f2o_kernel<<<blocks, threads>>>(src, flow, out);
}

// round 9
// speedup vs baseline: 1.0095x; 1.0095x over previous
#include <cuda_runtime.h>

// SpatialTransformer: out = trilinear_sample(src, identity_grid + flow), border clamp.
// src:  [1,1,160,192,160] f32   d_in[0]
// flow: [1,3,160,192,160] f32   d_in[1]  (channel-planar: d,h,w displacement)
// grid: identity meshgrid       d_in[2]  (IGNORED - recomputed from indices)
// out:  [1,1,160,192,160] f32
//
// Math collapse (verified, rel_err 2.6e-5):
//   ux = (w + flow[2]) * W/(W-1) - 0.5 ; clamp [0, W-1]; trilinear w/ clamped +1.
//
// Model after R8: perf ~ (warps/SM) x (independent gathers/thread). ZB=4 f2
// pair-fetch (R7, 62us) had the MLP; its occ was capped at 68% by 40 regs.
// R9: keep ZB=4, move flow loads inside the unrolled loop (frees ~9 regs),
// cap with __launch_bounds__(256,7) -> 56 warps/SM (87.5%) with no spill.

#define DD 160
#define HH 192
#define WW 160
#define PLANE (HH * WW)
#define NN (DD * HH * WW)
#define ZB 4   // z-batch per thread

__global__ __launch_bounds__(256, 7) void st_warp_f2r_kernel(
    const float* __restrict__ src,
    const float* __restrict__ flow,
    float* __restrict__ out)
{
    const int tid = blockIdx.x * blockDim.x + threadIdx.x;
    if (tid >= NN / ZB) return;

    const int w  = tid % WW;
    const int t  = tid / WW;
    const int h  = t % HH;
    const int dg = t / HH;          // z-group, d = dg*ZB + k
    const int base = (dg * ZB * HH + h) * WW + w;

    const float sx = (float)WW / (float)(WW - 1);
    const float sy = (float)HH / (float)(HH - 1);
    const float sz = (float)DD / (float)(DD - 1);

    float res[ZB];
#pragma unroll
    for (int k = 0; k < ZB; k++) {
        const int d = dg * ZB + k;
        const int idx = base + k * PLANE;

        // flow loads inside the iteration: consumed immediately -> low reg pressure,
        // still coalesced (warp = 32 consecutive x).
        const float fd = __ldg(flow + idx);            // D-displacement
        const float fh = __ldg(flow + NN + idx);       // H-displacement
        const float fw = __ldg(flow + 2 * NN + idx);   // W-displacement

        float ux = ((float)w + fw) * sx - 0.5f;
        float uy = ((float)h + fh) * sy - 0.5f;
        float uz = ((float)d + fd) * sz - 0.5f;

        ux = fminf(fmaxf(ux, 0.0f), (float)(WW - 1));
        uy = fminf(fmaxf(uy, 0.0f), (float)(HH - 1));
        uz = fminf(fmaxf(uz, 0.0f), (float)(DD - 1));

        // coords >= 0 -> truncation == floor
        const int x0 = (int)ux;
        const int y0 = (int)uy;
        const int z0 = (int)uz;
        const float ax = ux - (float)x0;
        const float ay = uy - (float)y0;
        const float az = uz - (float)z0;

        const int x1 = min(x0 + 1, WW - 1);
        const int y1 = min(y0 + 1, HH - 1);
        const int z1 = min(z0 + 1, DD - 1);

        const int x0a = x0 & ~1;            // 8B-aligned pair start
        const bool odd = (x0 & 1) != 0;

        const int zy00 = (z0 * HH + y0) * WW;
        const int zy01 = (z0 * HH + y1) * WW;
        const int zy10 = (z1 * HH + y0) * WW;
        const int zy11 = (z1 * HH + y1) * WW;

        const float2 v00 = __ldg((const float2*)(src + zy00 + x0a));
        const float2 v01 = __ldg((const float2*)(src + zy01 + x0a));
        const float2 v10 = __ldg((const float2*)(src + zy10 + x0a));
        const float2 v11 = __ldg((const float2*)(src + zy11 + x0a));

        // predicated fix-up loads for odd x0 (pair straddles float2 boundary)
        float e00 = v00.y, e01 = v01.y, e10 = v10.y, e11 = v11.y;
        if (odd) e00 = __ldg(src + zy00 + x1);
        if (odd) e01 = __ldg(src + zy01 + x1);
        if (odd) e10 = __ldg(src + zy10 + x1);
        if (odd) e11 = __ldg(src + zy11 + x1);

        const float l00 = odd ? v00.y : v00.x;
        const float l01 = odd ? v01.y : v01.x;
        const float l10 = odd ? v10.y : v10.x;
        const float l11 = odd ? v11.y : v11.x;

        const float c00 = fmaf(ax, e00 - l00, l00);
        const float c01 = fmaf(ax, e01 - l01, l01);
        const float c10 = fmaf(ax, e10 - l10, l10);
        const float c11 = fmaf(ax, e11 - l11, l11);

        const float c0 = fmaf(ay, c01 - c00, c00);
        const float c1 = fmaf(ay, c11 - c10, c10);
        res[k] = fmaf(az, c1 - c0, c0);
    }

#pragma unroll
    for (int k = 0; k < ZB; k++)
        out[base + k * PLANE] = res[k];
}

extern "C" void kernel_launch(void* const* d_in, const int* in_sizes, int n_in,
                              void* d_out, int out_size)
{
    const float* src  = (const float*)d_in[0];
    const float* flow = (const float*)d_in[1];
    // d_in[2] (identity grid) intentionally unused — recomputed from indices.
    float* out = (float*)d_out;

    const int threads = 256;
    const int blocks = (NN / ZB + threads - 1) / threads;
    st_warp_f2r_kernel<<<blocks, threads>>>(src, flow, out);
}

// round 10
// speedup vs baseline: 1.0292x; 1.0195x over previous
#include <cuda_runtime.h>

// SpatialTransformer: out = trilinear_sample(src, identity_grid + flow), border clamp.
// src:  [1,1,160,192,160] f32   d_in[0]
// flow: [1,3,160,192,160] f32   d_in[1]  (channel-planar: d,h,w displacement)
// grid: identity meshgrid       d_in[2]  (IGNORED - recomputed from indices)
// out:  [1,1,160,192,160] f32
//
// Math collapse (verified, rel_err 2.6e-5):
//   ux = (w + flow[2]) * W/(W-1) - 0.5 ; clamp [0, W-1]; trilinear w/ clamped +1.
//
// R9 lessons: (a) occupancy does NOT help (R8/R9 regressions at occ ~90%);
// R7 structure (ZB=4, front-batched flow loads, no minblocks) is the winner.
// (b) remaining cost = L1 gather wavefronts: 4 aligned f2 + 4 half-active
// odd fix-ups ~= 6/voxel.
//
// R10 move: shifted shadow copy B[i] = src[i+1] (one-time kernel, __device__
// scratch). Any x-pair (x0,x0+1) is then ONE aligned float2:
//   x0 even -> (const float2*)(src + zy + x0)
//   x0 odd  -> (const float2*)(B   + zy + x0 - 1)   [B[x0-1]=src[x0], B[x0]=src[x0+1]]
// 4 gather loads/voxel, no fix-ups, no lo/hi selects.

#define DD 160
#define HH 192
#define WW 160
#define PLANE (HH * WW)
#define NN (DD * HH * WW)
#define ZB 4   // z-batch per thread

// shifted shadow of src (+ small tail pad, zero-filled by the copy kernel)
__device__ __align__(16) float g_srcB[NN + 4];

__global__ __launch_bounds__(256) void shift_copy_kernel(const float* __restrict__ src)
{
    const int i4 = blockIdx.x * blockDim.x + threadIdx.x;
    if (i4 >= (NN + 4) / 4) return;
    const int j = i4 * 4;

    float4 v;
    v.x = (j + 1 < NN) ? __ldg(src + j + 1) : 0.0f;
    v.y = (j + 2 < NN) ? __ldg(src + j + 2) : 0.0f;
    v.z = (j + 3 < NN) ? __ldg(src + j + 3) : 0.0f;
    v.w = (j + 4 < NN) ? __ldg(src + j + 4) : 0.0f;
    *(float4*)(g_srcB + j) = v;
}

__global__ __launch_bounds__(256) void st_warp_sh_kernel(
    const float* __restrict__ src,
    const float* __restrict__ flow,
    float* __restrict__ out)
{
    const int tid = blockIdx.x * blockDim.x + threadIdx.x;
    if (tid >= NN / ZB) return;

    const int w  = tid % WW;
    const int t  = tid / WW;
    const int h  = t % HH;
    const int dg = t / HH;          // z-group, d = dg*ZB + k
    const int base = (dg * ZB * HH + h) * WW + w;

    const float sx = (float)WW / (float)(WW - 1);
    const float sy = (float)HH / (float)(HH - 1);
    const float sz = (float)DD / (float)(DD - 1);

    // front-batched flow loads (R7 structure: one latency exposure, coalesced)
    float fdv[ZB], fhv[ZB], fwv[ZB];
#pragma unroll
    for (int k = 0; k < ZB; k++) {
        const int idx = base + k * PLANE;
        fdv[k] = __ldg(flow + idx);            // D-displacement
        fhv[k] = __ldg(flow + NN + idx);       // H-displacement
        fwv[k] = __ldg(flow + 2 * NN + idx);   // W-displacement
    }

    float res[ZB];
#pragma unroll
    for (int k = 0; k < ZB; k++) {
        const int d = dg * ZB + k;

        float ux = ((float)w + fwv[k]) * sx - 0.5f;
        float uy = ((float)h + fhv[k]) * sy - 0.5f;
        float uz = ((float)d + fdv[k]) * sz - 0.5f;

        ux = fminf(fmaxf(ux, 0.0f), (float)(WW - 1));
        uy = fminf(fmaxf(uy, 0.0f), (float)(HH - 1));
        uz = fminf(fmaxf(uz, 0.0f), (float)(DD - 1));

        // coords >= 0 -> truncation == floor
        const int x0 = (int)ux;
        const int y0 = (int)uy;
        const int z0 = (int)uz;
        const float ax = ux - (float)x0;
        const float ay = uy - (float)y0;
        const float az = uz - (float)z0;

        const int y1 = min(y0 + 1, HH - 1);
        const int z1 = min(z0 + 1, DD - 1);

        // pair base: one aligned float2 covers (x0, x0+1) in src (even x0)
        // or in the shifted shadow B (odd x0). When x0 == WW-1 (ax == 0) the
        // hi element is out-of-row garbage multiplied by exactly 0.
        const bool odd = (x0 & 1) != 0;
        const float* pb = odd ? (g_srcB + (x0 - 1)) : (src + x0);

        const int zy00 = (z0 * HH + y0) * WW;
        const int zy01 = (z0 * HH + y1) * WW;
        const int zy10 = (z1 * HH + y0) * WW;
        const int zy11 = (z1 * HH + y1) * WW;

        const float2 v00 = __ldg((const float2*)(pb + zy00));
        const float2 v01 = __ldg((const float2*)(pb + zy01));
        const float2 v10 = __ldg((const float2*)(pb + zy10));
        const float2 v11 = __ldg((const float2*)(pb + zy11));

        const float c00 = fmaf(ax, v00.y - v00.x, v00.x);
        const float c01 = fmaf(ax, v01.y - v01.x, v01.x);
        const float c10 = fmaf(ax, v10.y - v10.x, v10.x);
        const float c11 = fmaf(ax, v11.y - v11.x, v11.x);

        const float c0 = fmaf(ay, c01 - c00, c00);
        const float c1 = fmaf(ay, c11 - c10, c10);
        res[k] = fmaf(az, c1 - c0, c0);
    }

#pragma unroll
    for (int k = 0; k < ZB; k++)
        out[base + k * PLANE] = res[k];
}

extern "C" void kernel_launch(void* const* d_in, const int* in_sizes, int n_in,
                              void* d_out, int out_size)
{
    const float* src  = (const float*)d_in[0];
    const float* flow = (const float*)d_in[1];
    // d_in[2] (identity grid) intentionally unused — recomputed from indices.
    float* out = (float*)d_out;

    const int threads = 256;

    // 1) build shifted shadow copy (deterministic, graph-capturable)
    const int copy_blocks = ((NN + 4) / 4 + threads - 1) / threads;
    shift_copy_kernel<<<copy_blocks, threads>>>(src);

    // 2) warp kernel (same stream -> ordered after the copy)
    const int blocks = (NN / ZB + threads - 1) / threads;
    st_warp_sh_kernel<<<blocks, threads>>>(src, flow, out);
}

// round 11
// speedup vs baseline: 1.4406x; 1.3998x over previous
#include <cuda_runtime.h>

// SpatialTransformer: out = trilinear_sample(src, identity_grid + flow), border clamp.
// src:  [1,1,160,192,160] f32   d_in[0]
// flow: [1,3,160,192,160] f32   d_in[1]  (channel-planar: d,h,w displacement)
// grid: identity meshgrid       d_in[2]  (IGNORED - recomputed from indices)
// out:  [1,1,160,192,160] f32
//
// Math collapse (verified, rel_err 2.6e-5):
//   ux = (w + flow[2]) * W/(W-1) - 0.5 ; clamp [0, W-1]; trilinear w/ clamped +1.
//
// Model after R10: gathers are L1-miss dominated (random +-9 into 19.7MB vs
// 228KB L1); kernel is L2-bandwidth/latency bound. Load-count tricks (R6/R10)
// don't move it. R11: 3D-tiled block mapping (32x x 8h x 4z per block) to
// shrink the per-block gather footprint ~300KB -> ~127KB so L1 captures the
// ~8x cross-voxel corner reuse. Gather scheme = R7 (aligned float2 pair +
// 25% predicated fix-up, single src array, front-batched flow loads).

#define DD 160
#define HH 192
#define WW 160
#define PLANE (HH * WW)
#define NN (DD * HH * WW)
#define ZB 4   // z-batch per thread

__global__ void st_warp_tile_kernel(
    const float* __restrict__ src,
    const float* __restrict__ flow,
    float* __restrict__ out)
{
    // 3D tile: 32 (x) x 8 (h) x ZB (z) voxels per block, 256 threads
    const int w  = blockIdx.x * 32 + threadIdx.x;
    const int h  = blockIdx.y * 8 + threadIdx.y;
    const int d0 = blockIdx.z * ZB;
    const int base = (d0 * HH + h) * WW + w;

    const float sx = (float)WW / (float)(WW - 1);
    const float sy = (float)HH / (float)(HH - 1);
    const float sz = (float)DD / (float)(DD - 1);

    // front-batched flow loads (one latency exposure; warp-coalesced: tx fastest)
    float fdv[ZB], fhv[ZB], fwv[ZB];
#pragma unroll
    for (int k = 0; k < ZB; k++) {
        const int idx = base + k * PLANE;
        fdv[k] = __ldg(flow + idx);            // D-displacement
        fhv[k] = __ldg(flow + NN + idx);       // H-displacement
        fwv[k] = __ldg(flow + 2 * NN + idx);   // W-displacement
    }

    float res[ZB];
#pragma unroll
    for (int k = 0; k < ZB; k++) {
        const int d = d0 + k;

        float ux = ((float)w + fwv[k]) * sx - 0.5f;
        float uy = ((float)h + fhv[k]) * sy - 0.5f;
        float uz = ((float)d + fdv[k]) * sz - 0.5f;

        ux = fminf(fmaxf(ux, 0.0f), (float)(WW - 1));
        uy = fminf(fmaxf(uy, 0.0f), (float)(HH - 1));
        uz = fminf(fmaxf(uz, 0.0f), (float)(DD - 1));

        // coords >= 0 -> truncation == floor
        const int x0 = (int)ux;
        const int y0 = (int)uy;
        const int z0 = (int)uz;
        const float ax = ux - (float)x0;
        const float ay = uy - (float)y0;
        const float az = uz - (float)z0;

        const int x1 = min(x0 + 1, WW - 1);
        const int y1 = min(y0 + 1, HH - 1);
        const int z1 = min(z0 + 1, DD - 1);

        const int x0a = x0 & ~1;            // 8B-aligned pair start
        const bool odd = (x0 & 1) != 0;

        const int zy00 = (z0 * HH + y0) * WW;
        const int zy01 = (z0 * HH + y1) * WW;
        const int zy10 = (z1 * HH + y0) * WW;
        const int zy11 = (z1 * HH + y1) * WW;

        const float2 v00 = __ldg((const float2*)(src + zy00 + x0a));
        const float2 v01 = __ldg((const float2*)(src + zy01 + x0a));
        const float2 v10 = __ldg((const float2*)(src + zy10 + x0a));
        const float2 v11 = __ldg((const float2*)(src + zy11 + x0a));

        // predicated fix-up loads for odd x0 (pair straddles float2 boundary)
        float e00 = v00.y, e01 = v01.y, e10 = v10.y, e11 = v11.y;
        if (odd) e00 = __ldg(src + zy00 + x1);
        if (odd) e01 = __ldg(src + zy01 + x1);
        if (odd) e10 = __ldg(src + zy10 + x1);
        if (odd) e11 = __ldg(src + zy11 + x1);

        const float l00 = odd ? v00.y : v00.x;
        const float l01 = odd ? v01.y : v01.x;
        const float l10 = odd ? v10.y : v10.x;
        const float l11 = odd ? v11.y : v11.x;

        const float c00 = fmaf(ax, e00 - l00, l00);
        const float c01 = fmaf(ax, e01 - l01, l01);
        const float c10 = fmaf(ax, e10 - l10, l10);
        const float c11 = fmaf(ax, e11 - l11, l11);

        const float c0 = fmaf(ay, c01 - c00, c00);
        const float c1 = fmaf(ay, c11 - c10, c10);
        res[k] = fmaf(az, c1 - c0, c0);
    }

#pragma unroll
    for (int k = 0; k < ZB; k++)
        out[base + k * PLANE] = res[k];
}

extern "C" void kernel_launch(void* const* d_in, const int* in_sizes, int n_in,
                              void* d_out, int out_size)
{
    const float* src  = (const float*)d_in[0];
    const float* flow = (const float*)d_in[1];
    // d_in[2] (identity grid) intentionally unused — recomputed from indices.
    float* out = (float*)d_out;

    dim3 block(32, 8, 1);
    dim3 grid(WW / 32, HH / 8, DD / ZB);   // 5 x 24 x 40 = 4800 blocks
    st_warp_tile_kernel<<<grid, block>>>(src, flow, out);
}